// round 1
// baseline (speedup 1.0000x reference)
#include <cuda_runtime.h>
#include <math.h>

#define EPS   1e-5f
#define BB    8
#define CC    128
#define NNN   20000
#define NCHK  157      // ceil(20000/128)
#define SPA   6        // n-splits per (b,mat) in kproj  -> 6*3*8 = 144 CTAs
#define SPB   18       // n-splits per b in kattn/kout   -> 18*8  = 144 CTAs

// ---------------- scratch (device globals; no allocation) ----------------
__device__ float g_QS[BB * NNN * CC];          // [b][n][c]
__device__ float g_KK[BB * NNN * CC];          // [b][n][c]
__device__ float g_V [BB * CC  * NNN];         // [b][c][n]
__device__ float g_part[BB * SPB * CC * CC];   // [b][s][c][d]
__device__ float g_attnT[BB * CC * CC];        // [b][d][c]  (transposed softmax result)

// ---------------- packed f32x2 helpers (FFMA2) ----------------
__device__ __forceinline__ unsigned long long pk2(float lo, float hi) {
    unsigned long long r;
    asm("mov.b64 %0, {%1, %2};" : "=l"(r) : "r"(__float_as_uint(lo)), "r"(__float_as_uint(hi)));
    return r;
}
__device__ __forceinline__ void fma2(unsigned long long& d, unsigned long long a, unsigned long long b) {
    asm("fma.rn.f32x2 %0, %1, %2, %0;" : "+l"(d) : "l"(a), "l"(b));
}
__device__ __forceinline__ float2 up2(unsigned long long v) {
    unsigned int lo, hi;
    asm("mov.b64 {%0, %1}, %2;" : "=r"(lo), "=r"(hi) : "l"(v));
    return make_float2(__uint_as_float(lo), __uint_as_float(hi));
}

// 8(a) x 8(b) outer-product step; b-dim packed in pairs -> 32 FMA2 per call.
__device__ __forceinline__ void mm_step(unsigned long long* acc,
                                        float4 a0, float4 a1, float4 b0, float4 b1) {
    unsigned long long bp0 = pk2(b0.x, b0.y);
    unsigned long long bp1 = pk2(b0.z, b0.w);
    unsigned long long bp2 = pk2(b1.x, b1.y);
    unsigned long long bp3 = pk2(b1.z, b1.w);
    float av[8] = {a0.x, a0.y, a0.z, a0.w, a1.x, a1.y, a1.z, a1.w};
#pragma unroll
    for (int i = 0; i < 8; i++) {
        unsigned long long ap = pk2(av[i], av[i]);
        fma2(acc[i * 4 + 0], ap, bp0);
        fma2(acc[i * 4 + 1], ap, bp1);
        fma2(acc[i * 4 + 2], ap, bp2);
        fma2(acc[i * 4 + 3], ap, bp3);
    }
}

__device__ __forceinline__ void unpack_acc(const unsigned long long* acc, float r[8][8]) {
#pragma unroll
    for (int i = 0; i < 8; i++)
#pragma unroll
        for (int j = 0; j < 4; j++) {
            float2 f = up2(acc[i * 4 + j]);
            r[i][2 * j]     = f.x;
            r[i][2 * j + 1] = f.y;
        }
}

// ================= Kernel A: fused BN-folded projections =================
// grid (SPA, 3, BB). mat 0 -> QS (relu, /sqrt(C), n-major)
//                    mat 1 -> KK = relu(k) + graph_context (n-major)
//                    mat 2 -> V (relu, c-major)
__global__ __launch_bounds__(256) void kproj(
    const float* __restrict__ pc, const float* __restrict__ xg,
    const float* __restrict__ Wq, const float* __restrict__ gq, const float* __restrict__ bq,
    const float* __restrict__ mq, const float* __restrict__ vq,
    const float* __restrict__ Wk, const float* __restrict__ gk, const float* __restrict__ bk,
    const float* __restrict__ mk, const float* __restrict__ vk,
    const float* __restrict__ Wv, const float* __restrict__ gv, const float* __restrict__ bv,
    const float* __restrict__ mv, const float* __restrict__ vv,
    const float* __restrict__ Wg1, const float* __restrict__ bg1,
    const float* __restrict__ Wg2, const float* __restrict__ bg2)
{
    extern __shared__ float sm[];
    float* sW     = sm;                 // 128 x 132 (transposed, BN-scale folded)
    float* spc    = sW + 128 * 132;     // 128 x 128 pc chunk
    float* sbeta  = spc + 128 * 128;    // 128
    float* salpha = sbeta + 128;        // 128
    float* sg     = salpha + 128;       // 5 x 128 (g0,g1,g2,g3,bg1+bg2)
    float* sx     = sg + 5 * 128;       // 4 x 128 x-chunk

    const int tid = threadIdx.x;
    const int mat = blockIdx.y;
    const int b   = blockIdx.z;

    const float *W, *G, *Bi, *Mn, *Vr;
    float* outp;
    if (mat == 0)      { W = Wq; G = gq; Bi = bq; Mn = mq; Vr = vq; outp = g_QS; }
    else if (mat == 1) { W = Wk; G = gk; Bi = bk; Mn = mk; Vr = vk; outp = g_KK; }
    else               { W = Wv; G = gv; Bi = bv; Mn = mv; Vr = vv; outp = g_V;  }

    if (tid < 128) {
        float sc = G[tid] / sqrtf(Vr[tid] + EPS);
        float al = sc;
        float bb = Bi[tid] - Mn[tid] * sc;
        if (mat == 0) { const float it = 1.0f / sqrtf(128.0f); al *= it; bb *= it; }
        salpha[tid] = al;
        sbeta[tid]  = bb;
        if (mat == 1) {
            sg[tid]       = Wg1[2 * tid];
            sg[128 + tid] = Wg1[2 * tid + 1];
            sg[256 + tid] = Wg2[2 * tid];
            sg[384 + tid] = Wg2[2 * tid + 1];
            sg[512 + tid] = bg1[tid] + bg2[tid];
        }
    }
    __syncthreads();
    // W[o][c] -> sW[c][o] with scale folded (4-way STS conflict, one-time)
    for (int i = tid; i < 128 * 128; i += 256) {
        int o = i >> 7, c = i & 127;
        sW[c * 132 + o] = W[i] * salpha[o];
    }

    const int og = tid >> 4, ng = tid & 15;
    const int o0 = og * 8,  nl = ng * 8;

    for (int ch = blockIdx.x; ch < NCHK; ch += SPA) {
        const int n0 = ch << 7;
        __syncthreads();
        for (int i = tid; i < 128 * 128; i += 256) {
            int c = i >> 7, nn = i & 127;
            int n = n0 + nn;
            spc[i] = (n < NNN) ? pc[(size_t)(b * 128 + c) * NNN + n] : 0.f;
        }
        if (mat == 1) {
            for (int i = tid; i < 512; i += 256) {
                int chn = i >> 7, nn = i & 127;
                int n = n0 + nn;
                sx[i] = (n < NNN) ? xg[(size_t)(b * 4 + chn) * NNN + n] : 0.f;
            }
        }
        __syncthreads();

        unsigned long long acc[32];
#pragma unroll
        for (int i = 0; i < 32; i++) acc[i] = 0ull;

#pragma unroll 2
        for (int c = 0; c < 128; c++) {
            float4 a0 = *(const float4*)(sW + c * 132 + o0);
            float4 a1 = *(const float4*)(sW + c * 132 + o0 + 4);
            float4 b0 = *(const float4*)(spc + (c << 7) + nl);
            float4 b1 = *(const float4*)(spc + (c << 7) + nl + 4);
            mm_step(acc, a0, a1, b0, b1);
        }

        float r[8][8];
        unpack_acc(acc, r);

#pragma unroll
        for (int i = 0; i < 8; i++) {
            const int o = o0 + i;
            const float bb = sbeta[o];
            if (mat == 1) {
                const float c0 = sg[o], c1 = sg[128 + o], c2 = sg[256 + o],
                            c3 = sg[384 + o], bgs = sg[512 + o];
#pragma unroll
                for (int j = 0; j < 8; j++) {
                    int nn = nl + j;
                    float t = fmaxf(r[i][j] + bb, 0.f);
                    t += c0 * sx[nn] + c1 * sx[128 + nn] + c2 * sx[256 + nn]
                       + c3 * sx[384 + nn] + bgs;
                    r[i][j] = t;
                }
            } else {
#pragma unroll
                for (int j = 0; j < 8; j++) r[i][j] = fmaxf(r[i][j] + bb, 0.f);
            }
        }

        if (n0 + nl < NNN) {     // NNN % 8 == 0, (n0+nl) % 8 == 0 -> all 8 n valid
            if (mat < 2) {       // n-major [b][n][c]
                float* ob = outp + (size_t)b * NNN * 128;
#pragma unroll
                for (int j = 0; j < 8; j++) {
                    int n = n0 + nl + j;
                    *(float4*)(ob + (size_t)n * 128 + o0)
                        = make_float4(r[0][j], r[1][j], r[2][j], r[3][j]);
                    *(float4*)(ob + (size_t)n * 128 + o0 + 4)
                        = make_float4(r[4][j], r[5][j], r[6][j], r[7][j]);
                }
            } else {             // c-major [b][c][n]
                float* ob = outp + (size_t)b * 128 * NNN;
#pragma unroll
                for (int i = 0; i < 8; i++) {
                    int o = o0 + i;
                    *(float4*)(ob + (size_t)o * NNN + n0 + nl)
                        = make_float4(r[i][0], r[i][1], r[i][2], r[i][3]);
                    *(float4*)(ob + (size_t)o * NNN + n0 + nl + 4)
                        = make_float4(r[i][4], r[i][5], r[i][6], r[i][7]);
                }
            }
        }
    }
}

// ================= Kernel B: attn partials = QS . KK^T (split-K over n) =================
__global__ __launch_bounds__(256) void kattn()
{
    extern __shared__ float sm[];
    float* sq = sm;              // [nn][c]
    float* sk = sm + 128 * 128;  // [nn][d]
    const int tid = threadIdx.x;
    const int s = blockIdx.x, b = blockIdx.y;
    const int cg = tid >> 4, dg = tid & 15;
    const int c0 = cg * 8,  d0 = dg * 8;

    unsigned long long acc[32];
#pragma unroll
    for (int i = 0; i < 32; i++) acc[i] = 0ull;

    for (int ch = s; ch < NCHK; ch += SPB) {
        const int n0 = ch << 7;
        __syncthreads();
        for (int i = tid; i < 128 * 128; i += 256) {
            int nn = i >> 7;
            int n  = n0 + nn;
            if (n < NNN) {
                size_t base = (size_t)(b * NNN + n) * 128 + (i & 127);
                sq[i] = g_QS[base];
                sk[i] = g_KK[base];
            } else {
                sq[i] = 0.f;
                sk[i] = 0.f;
            }
        }
        __syncthreads();
#pragma unroll 2
        for (int nn = 0; nn < 128; nn++) {
            float4 a0 = *(const float4*)(sq + (nn << 7) + c0);
            float4 a1 = *(const float4*)(sq + (nn << 7) + c0 + 4);
            float4 b0 = *(const float4*)(sk + (nn << 7) + d0);
            float4 b1 = *(const float4*)(sk + (nn << 7) + d0 + 4);
            mm_step(acc, a0, a1, b0, b1);
        }
    }

    float r[8][8];
    unpack_acc(acc, r);
    float* ob = g_part + (size_t)(b * SPB + s) * 128 * 128;
#pragma unroll
    for (int i = 0; i < 8; i++) {
        *(float4*)(ob + (size_t)(c0 + i) * 128 + d0)
            = make_float4(r[i][0], r[i][1], r[i][2], r[i][3]);
        *(float4*)(ob + (size_t)(c0 + i) * 128 + d0 + 4)
            = make_float4(r[i][4], r[i][5], r[i][6], r[i][7]);
    }
}

// ================= Kernel S: reduce partials + softmax, write transposed =================
__global__ __launch_bounds__(256) void ksoft()
{
    const int bx = blockIdx.x;
    const int b = bx >> 4, rb = bx & 15;
    const int w = threadIdx.x >> 5, lane = threadIdx.x & 31;
    const int c = rb * 8 + w;

    float v[4];
#pragma unroll
    for (int k = 0; k < 4; k++) {
        int d = k * 32 + lane;
        float acc = 0.f;
        for (int s = 0; s < SPB; s++)
            acc += g_part[(size_t)((b * SPB + s) * 128 + c) * 128 + d];
        v[k] = acc;
    }
    float m = fmaxf(fmaxf(v[0], v[1]), fmaxf(v[2], v[3]));
#pragma unroll
    for (int off = 16; off; off >>= 1) m = fmaxf(m, __shfl_xor_sync(0xffffffffu, m, off));
    float e[4], sum = 0.f;
#pragma unroll
    for (int k = 0; k < 4; k++) { e[k] = expf(v[k] - m); sum += e[k]; }
#pragma unroll
    for (int off = 16; off; off >>= 1) sum += __shfl_xor_sync(0xffffffffu, sum, off);
    const float inv = 1.f / sum;
#pragma unroll
    for (int k = 0; k < 4; k++) {
        int d = k * 32 + lane;
        g_attnT[(size_t)(b * 128 + d) * 128 + c] = e[k] * inv;
    }
}

// ================= Kernel C: out = attn . V =================
__global__ __launch_bounds__(256) void kout(float* __restrict__ out)
{
    extern __shared__ float sm[];
    float* sA = sm;              // attnT [d][c]
    float* sV = sm + 128 * 128;  // [d][nn]
    const int tid = threadIdx.x;
    const int s = blockIdx.x, b = blockIdx.y;
    const int cg = tid >> 4, ng = tid & 15;
    const int c0 = cg * 8,  nl = ng * 8;

    for (int i = tid; i < 128 * 128; i += 256)
        sA[i] = g_attnT[(size_t)b * 128 * 128 + i];

    for (int ch = s; ch < NCHK; ch += SPB) {
        const int n0 = ch << 7;
        __syncthreads();
        for (int i = tid; i < 128 * 128; i += 256) {
            int d = i >> 7, nn = i & 127;
            int n = n0 + nn;
            sV[i] = (n < NNN) ? g_V[(size_t)(b * 128 + d) * NNN + n] : 0.f;
        }
        __syncthreads();

        unsigned long long acc[32];
#pragma unroll
        for (int i = 0; i < 32; i++) acc[i] = 0ull;

#pragma unroll 2
        for (int d = 0; d < 128; d++) {
            float4 a0 = *(const float4*)(sA + (d << 7) + c0);
            float4 a1 = *(const float4*)(sA + (d << 7) + c0 + 4);
            float4 b0 = *(const float4*)(sV + (d << 7) + nl);
            float4 b1 = *(const float4*)(sV + (d << 7) + nl + 4);
            mm_step(acc, a0, a1, b0, b1);
        }

        float r[8][8];
        unpack_acc(acc, r);
        if (n0 + nl < NNN) {
#pragma unroll
            for (int i = 0; i < 8; i++) {
                int c = c0 + i;
                *(float4*)(out + (size_t)(b * 128 + c) * NNN + n0 + nl)
                    = make_float4(r[i][0], r[i][1], r[i][2], r[i][3]);
                *(float4*)(out + (size_t)(b * 128 + c) * NNN + n0 + nl + 4)
                    = make_float4(r[i][4], r[i][5], r[i][6], r[i][7]);
            }
        }
    }
}

// ================= launch =================
extern "C" void kernel_launch(void* const* d_in, const int* in_sizes, int n_in,
                              void* d_out, int out_size)
{
    const float* pc  = (const float*)d_in[0];
    const float* xg  = (const float*)d_in[1];
    const float* Wq  = (const float*)d_in[2];
    const float* gq  = (const float*)d_in[3];
    const float* bq  = (const float*)d_in[4];
    const float* mq  = (const float*)d_in[5];
    const float* vq  = (const float*)d_in[6];
    const float* Wk  = (const float*)d_in[7];
    const float* gk  = (const float*)d_in[8];
    const float* bk  = (const float*)d_in[9];
    const float* mk  = (const float*)d_in[10];
    const float* vk  = (const float*)d_in[11];
    const float* Wv  = (const float*)d_in[12];
    const float* gv  = (const float*)d_in[13];
    const float* bv  = (const float*)d_in[14];
    const float* mv  = (const float*)d_in[15];
    const float* vv  = (const float*)d_in[16];
    const float* Wg1 = (const float*)d_in[17];
    const float* bg1 = (const float*)d_in[18];
    const float* Wg2 = (const float*)d_in[19];
    const float* bg2 = (const float*)d_in[20];
    float* out = (float*)d_out;

    constexpr int SMEM_A = (128 * 132 + 128 * 128 + 128 + 128 + 5 * 128 + 4 * 128) * 4;
    constexpr int SMEM_G = 2 * 128 * 128 * 4;
    cudaFuncSetAttribute(kproj, cudaFuncAttributeMaxDynamicSharedMemorySize, SMEM_A);
    cudaFuncSetAttribute(kattn, cudaFuncAttributeMaxDynamicSharedMemorySize, SMEM_G);
    cudaFuncSetAttribute(kout,  cudaFuncAttributeMaxDynamicSharedMemorySize, SMEM_G);

    kproj<<<dim3(SPA, 3, BB), 256, SMEM_A>>>(pc, xg,
        Wq, gq, bq, mq, vq,
        Wk, gk, bk, mk, vk,
        Wv, gv, bv, mv, vv,
        Wg1, bg1, Wg2, bg2);
    kattn<<<dim3(SPB, BB), 256, SMEM_G>>>();
    ksoft<<<dim3(BB * 16), 256>>>();
    kout<<<dim3(SPB, BB), 256, SMEM_G>>>(out);
}